// round 8
// baseline (speedup 1.0000x reference)
#include <cuda_runtime.h>
#include <math.h>

// Problem constants
#define NB   8
#define T1   512
#define T2   128
#define EE   64      // E
#define G3   192     // 3*E
#define DLN  256
#define CTXD 128     // 2*E
#define VOC  129     // LA+1

// Scratch (device globals)
__device__ float g_tab[2 * VOC * G3];        // per-dir input-gate table
__device__ float g_ctx[NB * T2 * CTXD];      // [b][s][fwd|bwd]
__device__ float g_Q00[NB * T2 * EE];
__device__ float g_Qm [NB * T2 * EE];
__device__ float g_Q11[NB * T2 * EE];
__device__ float g_cs[NB * T2];              // ctx . w_c
__device__ float g_bias2[EE];

__device__ __forceinline__ float fsigmoid(float v) {
    return __fdividef(1.0f, 1.0f + __expf(-v));
}
__device__ __forceinline__ float ftanh(float v) {
    return fmaf(2.0f, __fdividef(1.0f, 1.0f + __expf(-2.0f * v)), -1.0f);
}

// ---------------------------------------------------------------------------
// Kernel T: input-gate table  tab[dir][c][u] = emb[c]@K_dir + b0[u]
// grid (129,2), block 192
// ---------------------------------------------------------------------------
__global__ void k_tab(const float* __restrict__ emb_table,
                      const float* __restrict__ Kf, const float* __restrict__ bf,
                      const float* __restrict__ Kb, const float* __restrict__ bb) {
    int c = blockIdx.x, dir = blockIdx.y;
    int u = threadIdx.x;
    __shared__ float e_sm[EE];
    if (u < EE) e_sm[u] = emb_table[c * EE + u];
    __syncthreads();
    const float* K = dir ? Kb : Kf;
    float a0 = (dir ? bb : bf)[u], a1 = 0.f, a2 = 0.f, a3 = 0.f;
    const float4* e4 = (const float4*)e_sm;
#pragma unroll
    for (int k = 0; k < 16; k++) {
        float4 hv = e4[k];
        int e = 4 * k;
        a0 = fmaf(hv.x, K[(e + 0) * G3 + u], a0);
        a1 = fmaf(hv.y, K[(e + 1) * G3 + u], a1);
        a2 = fmaf(hv.z, K[(e + 2) * G3 + u], a2);
        a3 = fmaf(hv.w, K[(e + 3) * G3 + u], a3);
    }
    g_tab[(dir * VOC + c) * G3 + u] = (a0 + a1) + (a2 + a3);
}

// ---------------------------------------------------------------------------
// Kernel G: GRU. grid (8,2), block 384 (= 192 cols x 2 e-halves).
// All x pre-staged in smem; 2 barriers/step; 4-acc matvec + 1 shfl.
// ---------------------------------------------------------------------------
__global__ void __launch_bounds__(384) k_gru(const int* __restrict__ char_seq,
                      const float* __restrict__ Rf, const float* __restrict__ bf,
                      const float* __restrict__ Rb, const float* __restrict__ bb) {
    extern __shared__ float x_sm[];              // [128][192]
    __shared__ float h_sm[EE];
    __shared__ float z_sm[EE];
    __shared__ float r_sm[EE];
    __shared__ int   s_char[T2];
    int b = blockIdx.x, dir = blockIdx.y;
    int tid = threadIdx.x;
    int col = tid >> 1, half = tid & 1;
    int gate = col >> 6, i = col & 63;

    const float* R    = dir ? Rb : Rf;
    const float* bias = dir ? bb : bf;
    float Rc[32];
#pragma unroll
    for (int e = 0; e < 32; e++) Rc[e] = R[(half * 32 + e) * G3 + col];
    float bcol = (half == 0) ? bias[G3 + col] : 0.0f;

    if (tid < T2) s_char[tid] = char_seq[b * T2 + tid];
    if (tid < EE) h_sm[tid] = 0.0f;
    __syncthreads();

    const float* tab = g_tab + dir * VOC * G3;
    for (int idx = tid; idx < T2 * G3; idx += 384) {
        int row = idx / G3, cc = idx - row * G3;
        x_sm[idx] = tab[s_char[row] * G3 + cc];
    }
    __syncthreads();

    float h = 0.0f, y = 0.0f;
    for (int t = 0; t < T2; t++) {
        int tt = dir ? (T2 - 1 - t) : t;
        float x = x_sm[tt * G3 + col];
        const float4* h4 = (const float4*)h_sm + half * 8;
        float a0 = bcol, a1 = 0.f, a2 = 0.f, a3 = 0.f;
#pragma unroll
        for (int k = 0; k < 8; k++) {
            float4 hv = h4[k];
            a0 = fmaf(hv.x, Rc[4 * k + 0], a0);
            a1 = fmaf(hv.y, Rc[4 * k + 1], a1);
            a2 = fmaf(hv.z, Rc[4 * k + 2], a2);
            a3 = fmaf(hv.w, Rc[4 * k + 3], a3);
        }
        float sum = (a0 + a1) + (a2 + a3);
        sum += __shfl_xor_sync(0xffffffffu, sum, 1);    // full rg(col)
        if (half == 0) {
            if (gate == 0)      z_sm[i] = fsigmoid(x + sum);
            else if (gate == 1) r_sm[i] = fsigmoid(x + sum);
        }
        __syncthreads();
        if (half == 0 && gate == 2) {
            float hh = ftanh(fmaf(r_sm[i], sum, x));
            float z  = z_sm[i];
            float hn = fmaf(z, h - hh, hh);              // z*h + (1-z)*hh
            if (s_char[tt] != 0) { h = hn; y = hn; }
            h_sm[i] = h;
            g_ctx[(b * T2 + tt) * CTXD + dir * EE + i] = y;
        }
        __syncthreads();
    }
}

// ---------------------------------------------------------------------------
// Kernel PQ: per (b,s): cs = ctx.w_c ; P0/P1 = ctx@W1 ; Q00/Qm/Q11 = P@W2
// grid 1024, block 128
// ---------------------------------------------------------------------------
__global__ void k_pq(const float* __restrict__ conv1_w,
                     const float* __restrict__ conv2_w,
                     const float* __restrict__ conv1_b,
                     const float* __restrict__ conv2_b,
                     const float* __restrict__ w_char) {
    int bs = blockIdx.x;
    int tid = threadIdx.x;
    __shared__ float c_sm[CTXD];
    __shared__ float wsum[4];
    __shared__ float p_sm[2][EE];
    __shared__ float q01_sm[EE];

    float cv = g_ctx[bs * CTXD + tid];
    c_sm[tid] = cv;
    float pv = cv * w_char[DLN + tid];
#pragma unroll
    for (int off = 16; off; off >>= 1) pv += __shfl_xor_sync(0xffffffffu, pv, off);
    if ((tid & 31) == 0) wsum[tid >> 5] = pv;
    __syncthreads();
    if (tid == 0) g_cs[bs] = (wsum[0] + wsum[1]) + (wsum[2] + wsum[3]);

    int half = tid >> 6, o = tid & 63;
    const float* W = conv1_w + half * CTXD * EE;
    float a0 = 0.f, a1 = 0.f, a2 = 0.f, a3 = 0.f;
    const float4* c4 = (const float4*)c_sm;
#pragma unroll
    for (int k = 0; k < CTXD / 4; k++) {
        float4 hv = c4[k];
        int c = 4 * k;
        a0 = fmaf(hv.x, W[(c + 0) * EE + o], a0);
        a1 = fmaf(hv.y, W[(c + 1) * EE + o], a1);
        a2 = fmaf(hv.z, W[(c + 2) * EE + o], a2);
        a3 = fmaf(hv.w, W[(c + 3) * EE + o], a3);
    }
    p_sm[half][o] = (a0 + a1) + (a2 + a3);
    __syncthreads();

    const float* W20 = conv2_w;
    const float* W21 = conv2_w + EE * EE;
    const float* P = p_sm[half];
    float qa0 = 0.f, qa1 = 0.f, qb0 = 0.f, qb1 = 0.f;
#pragma unroll
    for (int k = 0; k < EE; k += 2) {
        float pA = P[k], pB = P[k + 1];
        qa0 = fmaf(pA, W20[k * EE + o], qa0);
        qb0 = fmaf(pA, W21[k * EE + o], qb0);
        qa1 = fmaf(pB, W20[(k + 1) * EE + o], qa1);
        qb1 = fmaf(pB, W21[(k + 1) * EE + o], qb1);
    }
    float qW20 = qa0 + qa1;   // P@W20
    float qW21 = qb0 + qb1;   // P@W21
    if (half == 0) {
        g_Q00[bs * EE + o] = qW20;
        q01_sm[o] = qW21;
    }
    __syncthreads();
    if (half == 1) {
        g_Qm [bs * EE + o] = qW20 + q01_sm[o];   // P1@W20 + P0@W21
        g_Q11[bs * EE + o] = qW21;
    }
    if (bs == 0 && half == 0) {
        float bb2 = conv2_b[o];
#pragma unroll
        for (int k = 0; k < EE; k++)
            bb2 = fmaf(conv1_b[k], W20[k * EE + o] + W21[k * EE + o], bb2);
        g_bias2[o] = bb2;
    }
}

// ---------------------------------------------------------------------------
// Kernel D: fused a-dot + char_weights + base/slope max over s.
// grid (8,32), block 256: 16 t per block, 4 t per thread (tq = tid>>6).
// ---------------------------------------------------------------------------
__global__ void __launch_bounds__(256) k_main(const float* __restrict__ lstm,
                                              const float* __restrict__ w_char,
                                              const float* __restrict__ b_char,
                                              float* __restrict__ out_final,
                                              float* __restrict__ out_cw) {
    int b = blockIdx.x, t0 = blockIdx.y * 16;
    int tid = threadIdx.x;
    __shared__ float A_sm[16];
    __shared__ float garr[T2];

    // Phase A: garr[s] = cs + w_i*s
    float wi = w_char[DLN + CTXD + 1];
    if (tid < T2) garr[tid] = g_cs[b * T2 + tid] + wi * (float)tid;

    // Phase A2: A_sm[grp] = lstm[b, t0+grp] . w_l + w_t*(t0+grp) + bc
    // 16 groups of 16 threads; each thread loads 4 float4 (16 floats).
    {
        int grp = tid >> 4, l16 = tid & 15;
        const float4* row4 = (const float4*)(lstm + ((long)(b * T1 + t0 + grp)) * DLN);
        const float4* wl4  = (const float4*)w_char;
        float pv = 0.0f;
#pragma unroll
        for (int k = 0; k < 4; k++) {
            float4 rv = row4[l16 * 4 + k], wv = wl4[l16 * 4 + k];
            pv += rv.x * wv.x + rv.y * wv.y + rv.z * wv.z + rv.w * wv.w;
        }
#pragma unroll
        for (int off = 8; off; off >>= 1)
            pv += __shfl_xor_sync(0xffffffffu, pv, off);
        if (l16 == 0)
            A_sm[grp] = pv + w_char[DLN + CTXD] * (float)(t0 + grp) + b_char[0];
    }
    __syncthreads();

    // Phase B: char_weights = A + g[s]   (16 t x 128 s, coalesced, unrolled)
    {
        float* cwb = out_cw + ((long)(b * T1 + t0)) * T2;
#pragma unroll
        for (int it = 0; it < 8; it++) {
            int idx = tid + it * 256;
            int tl = idx >> 7, s = idx & (T2 - 1);
            cwb[tl * T2 + s] = A_sm[tl] + garr[s];
        }
    }

    // Phase C: max over s with base/slope sharing across 4 t's per thread.
    int tq = tid >> 6, o = tid & 63;
    float A0 = A_sm[tq + 0], A1 = A_sm[tq + 4], A2 = A_sm[tq + 8], A3 = A_sm[tq + 12];
    const float* Q00 = g_Q00 + b * T2 * EE + o;
    const float* Qm  = g_Qm  + b * T2 * EE + EE + o;        // at s+1
    const float* Q11 = g_Q11 + b * T2 * EE + 2 * EE + o;    // at s+2
    float b2 = g_bias2[o];
    float m0 = -INFINITY, m1 = -INFINITY, m2 = -INFINITY, m3 = -INFINITY;
#pragma unroll 2
    for (int s = 0; s < T2 - 2; s++) {
        float q0 = Q00[s * EE];
        float qm = Qm [s * EE];
        float q1 = Q11[s * EE];
        float slope = (q0 + qm) + q1;
        float base  = fmaf(garr[s], q0, fmaf(garr[s + 1], qm, fmaf(garr[s + 2], q1, b2)));
        m0 = fmaxf(m0, fmaf(A0, slope, base));
        m1 = fmaxf(m1, fmaf(A1, slope, base));
        m2 = fmaxf(m2, fmaf(A2, slope, base));
        m3 = fmaxf(m3, fmaf(A3, slope, base));
    }
    long ob = (long)(b * T1 + t0) * EE + o;
    out_final[ob + (tq + 0)  * EE] = m0;
    out_final[ob + (tq + 4)  * EE] = m1;
    out_final[ob + (tq + 8)  * EE] = m2;
    out_final[ob + (tq + 12) * EE] = m3;
}

// ---------------------------------------------------------------------------
extern "C" void kernel_launch(void* const* d_in, const int* in_sizes, int n_in,
                              void* d_out, int out_size) {
    const float* lstm     = (const float*)d_in[0];
    const int*   char_seq = (const int*)  d_in[1];
    const float* emb      = (const float*)d_in[2];
    const float* Kf       = (const float*)d_in[3];
    const float* Rf       = (const float*)d_in[4];
    const float* bf       = (const float*)d_in[5];
    const float* Kb       = (const float*)d_in[6];
    const float* Rb       = (const float*)d_in[7];
    const float* bb       = (const float*)d_in[8];
    const float* w_char   = (const float*)d_in[9];
    const float* b_char   = (const float*)d_in[10];
    const float* conv1_w  = (const float*)d_in[11];
    const float* conv1_b  = (const float*)d_in[12];
    const float* conv2_w  = (const float*)d_in[13];
    const float* conv2_b  = (const float*)d_in[14];

    float* out_final = (float*)d_out;                 // (8,512,64)
    float* out_cw    = out_final + NB * T1 * EE;      // (8,512,128,1)

    (void)cudaFuncSetAttribute(k_gru, cudaFuncAttributeMaxDynamicSharedMemorySize,
                               T2 * G3 * (int)sizeof(float));

    k_tab<<<dim3(VOC, 2), G3>>>(emb, Kf, bf, Kb, bb);
    k_gru<<<dim3(NB, 2), 384, T2 * G3 * sizeof(float)>>>(char_seq, Rf, bf, Rb, bb);
    k_pq<<<NB * T2, CTXD>>>(conv1_w, conv2_w, conv1_b, conv2_b, w_char);
    k_main<<<dim3(NB, T1 / 16), 256>>>(lstm, w_char, b_char, out_final, out_cw);
}

// round 9
// speedup vs baseline: 1.1059x; 1.1059x over previous
#include <cuda_runtime.h>
#include <math.h>

// Problem constants
#define NB   8
#define T1   512
#define T2   128
#define EE   64      // E
#define G3   192     // 3*E
#define DLN  256
#define CTXD 128     // 2*E
#define VOC  129     // LA+1
#define NS   126     // T2-2 valid conv output positions

// Scratch (device globals)
__device__ float g_tab[2 * VOC * G3];        // per-dir input-gate table
__device__ float g_ctx[NB * T2 * CTXD];      // [b][s][fwd|bwd]
__device__ float g_Q00[NB * T2 * EE];
__device__ float g_Qm [NB * T2 * EE];
__device__ float g_Q11[NB * T2 * EE];
__device__ float g_cs[NB * T2];              // ctx . w_c
__device__ float g_bias2[EE];

__device__ __forceinline__ float fsigmoid(float v) {
    return __fdividef(1.0f, 1.0f + __expf(-v));
}
__device__ __forceinline__ float ftanh(float v) {
    return fmaf(2.0f, __fdividef(1.0f, 1.0f + __expf(-2.0f * v)), -1.0f);
}

// ---------------------------------------------------------------------------
// Kernel T: input-gate table  tab[dir][c][u] = emb[c]@K_dir + b0[u]
// grid (129,2), block 192
// ---------------------------------------------------------------------------
__global__ void k_tab(const float* __restrict__ emb_table,
                      const float* __restrict__ Kf, const float* __restrict__ bf,
                      const float* __restrict__ Kb, const float* __restrict__ bb) {
    int c = blockIdx.x, dir = blockIdx.y;
    int u = threadIdx.x;
    __shared__ float e_sm[EE];
    if (u < EE) e_sm[u] = emb_table[c * EE + u];
    __syncthreads();
    const float* K = dir ? Kb : Kf;
    float a0 = (dir ? bb : bf)[u], a1 = 0.f, a2 = 0.f, a3 = 0.f;
    const float4* e4 = (const float4*)e_sm;
#pragma unroll
    for (int k = 0; k < 16; k++) {
        float4 hv = e4[k];
        int e = 4 * k;
        a0 = fmaf(hv.x, K[(e + 0) * G3 + u], a0);
        a1 = fmaf(hv.y, K[(e + 1) * G3 + u], a1);
        a2 = fmaf(hv.z, K[(e + 2) * G3 + u], a2);
        a3 = fmaf(hv.w, K[(e + 3) * G3 + u], a3);
    }
    g_tab[(dir * VOC + c) * G3 + u] = (a0 + a1) + (a2 + a3);
}

// ---------------------------------------------------------------------------
// Kernel G: GRU. grid (8,2), block 384 (= 192 cols x 2 e-halves).
// All x pre-staged in smem; 2 barriers/step; 4-acc matvec + 1 shfl.
// ---------------------------------------------------------------------------
__global__ void __launch_bounds__(384) k_gru(const int* __restrict__ char_seq,
                      const float* __restrict__ Rf, const float* __restrict__ bf,
                      const float* __restrict__ Rb, const float* __restrict__ bb) {
    extern __shared__ float x_sm[];              // [128][192]
    __shared__ float h_sm[EE];
    __shared__ float z_sm[EE];
    __shared__ float r_sm[EE];
    __shared__ int   s_char[T2];
    int b = blockIdx.x, dir = blockIdx.y;
    int tid = threadIdx.x;
    int col = tid >> 1, half = tid & 1;
    int gate = col >> 6, i = col & 63;

    const float* R    = dir ? Rb : Rf;
    const float* bias = dir ? bb : bf;
    float Rc[32];
#pragma unroll
    for (int e = 0; e < 32; e++) Rc[e] = R[(half * 32 + e) * G3 + col];
    float bcol = (half == 0) ? bias[G3 + col] : 0.0f;

    if (tid < T2) s_char[tid] = char_seq[b * T2 + tid];
    if (tid < EE) h_sm[tid] = 0.0f;
    __syncthreads();

    const float* tab = g_tab + dir * VOC * G3;
    for (int idx = tid; idx < T2 * G3; idx += 384) {
        int row = idx / G3, cc = idx - row * G3;
        x_sm[idx] = tab[s_char[row] * G3 + cc];
    }
    __syncthreads();

    float h = 0.0f, y = 0.0f;
    for (int t = 0; t < T2; t++) {
        int tt = dir ? (T2 - 1 - t) : t;
        float x = x_sm[tt * G3 + col];
        const float4* h4 = (const float4*)h_sm + half * 8;
        float a0 = bcol, a1 = 0.f, a2 = 0.f, a3 = 0.f;
#pragma unroll
        for (int k = 0; k < 8; k++) {
            float4 hv = h4[k];
            a0 = fmaf(hv.x, Rc[4 * k + 0], a0);
            a1 = fmaf(hv.y, Rc[4 * k + 1], a1);
            a2 = fmaf(hv.z, Rc[4 * k + 2], a2);
            a3 = fmaf(hv.w, Rc[4 * k + 3], a3);
        }
        float sum = (a0 + a1) + (a2 + a3);
        sum += __shfl_xor_sync(0xffffffffu, sum, 1);    // full rg(col)
        if (half == 0) {
            if (gate == 0)      z_sm[i] = fsigmoid(x + sum);
            else if (gate == 1) r_sm[i] = fsigmoid(x + sum);
        }
        __syncthreads();
        if (half == 0 && gate == 2) {
            float hh = ftanh(fmaf(r_sm[i], sum, x));
            float z  = z_sm[i];
            float hn = fmaf(z, h - hh, hh);              // z*h + (1-z)*hh
            if (s_char[tt] != 0) { h = hn; y = hn; }
            h_sm[i] = h;
            g_ctx[(b * T2 + tt) * CTXD + dir * EE + i] = y;
        }
        __syncthreads();
    }
}

// ---------------------------------------------------------------------------
// Kernel PQ: per (b,s): cs = ctx.w_c ; P0/P1 = ctx@W1 ; Q00/Qm/Q11 = P@W2
// grid 1024, block 128
// ---------------------------------------------------------------------------
__global__ void k_pq(const float* __restrict__ conv1_w,
                     const float* __restrict__ conv2_w,
                     const float* __restrict__ conv1_b,
                     const float* __restrict__ conv2_b,
                     const float* __restrict__ w_char) {
    int bs = blockIdx.x;
    int tid = threadIdx.x;
    __shared__ float c_sm[CTXD];
    __shared__ float wsum[4];
    __shared__ float p_sm[2][EE];
    __shared__ float q01_sm[EE];

    float cv = g_ctx[bs * CTXD + tid];
    c_sm[tid] = cv;
    float pv = cv * w_char[DLN + tid];
#pragma unroll
    for (int off = 16; off; off >>= 1) pv += __shfl_xor_sync(0xffffffffu, pv, off);
    if ((tid & 31) == 0) wsum[tid >> 5] = pv;
    __syncthreads();
    if (tid == 0) g_cs[bs] = (wsum[0] + wsum[1]) + (wsum[2] + wsum[3]);

    int half = tid >> 6, o = tid & 63;
    const float* W = conv1_w + half * CTXD * EE;
    float a0 = 0.f, a1 = 0.f, a2 = 0.f, a3 = 0.f;
    const float4* c4 = (const float4*)c_sm;
#pragma unroll
    for (int k = 0; k < CTXD / 4; k++) {
        float4 hv = c4[k];
        int c = 4 * k;
        a0 = fmaf(hv.x, W[(c + 0) * EE + o], a0);
        a1 = fmaf(hv.y, W[(c + 1) * EE + o], a1);
        a2 = fmaf(hv.z, W[(c + 2) * EE + o], a2);
        a3 = fmaf(hv.w, W[(c + 3) * EE + o], a3);
    }
    p_sm[half][o] = (a0 + a1) + (a2 + a3);
    __syncthreads();

    const float* W20 = conv2_w;
    const float* W21 = conv2_w + EE * EE;
    const float* P = p_sm[half];
    float qa0 = 0.f, qa1 = 0.f, qb0 = 0.f, qb1 = 0.f;
#pragma unroll
    for (int k = 0; k < EE; k += 2) {
        float pA = P[k], pB = P[k + 1];
        qa0 = fmaf(pA, W20[k * EE + o], qa0);
        qb0 = fmaf(pA, W21[k * EE + o], qb0);
        qa1 = fmaf(pB, W20[(k + 1) * EE + o], qa1);
        qb1 = fmaf(pB, W21[(k + 1) * EE + o], qb1);
    }
    float qW20 = qa0 + qa1;   // P@W20
    float qW21 = qb0 + qb1;   // P@W21
    if (half == 0) {
        g_Q00[bs * EE + o] = qW20;
        q01_sm[o] = qW21;
    }
    __syncthreads();
    if (half == 1) {
        g_Qm [bs * EE + o] = qW20 + q01_sm[o];   // P1@W20 + P0@W21
        g_Q11[bs * EE + o] = qW21;
    }
    if (bs == 0 && half == 0) {
        float bb2 = conv2_b[o];
#pragma unroll
        for (int k = 0; k < EE; k++)
            bb2 = fmaf(conv1_b[k], W20[k * EE + o] + W21[k * EE + o], bb2);
        g_bias2[o] = bb2;
    }
}

// ---------------------------------------------------------------------------
// Kernel D: smem slope/base slab + 8-way t-register-blocked max-plus.
// grid (8 b, 8 tb), block 512 (8 t-groups x 64 o). 64 t per block.
// Dynamic smem: float2 sb[126*64] (slope, base) = 63 KB.
// ---------------------------------------------------------------------------
__global__ void __launch_bounds__(512) k_main(const float* __restrict__ lstm,
                                              const float* __restrict__ w_char,
                                              const float* __restrict__ b_char,
                                              float* __restrict__ out_final,
                                              float* __restrict__ out_cw) {
    extern __shared__ float2 sb_sm[];            // [126*64] {slope, base}
    __shared__ float A_sm[64];
    __shared__ float garr[T2];
    int b = blockIdx.x, t0 = blockIdx.y * 64;
    int tid = threadIdx.x;

    // Phase A: garr[s] = cs + w_i*s
    float wi = w_char[DLN + CTXD + 1];
    if (tid < T2) garr[tid] = g_cs[b * T2 + tid] + wi * (float)tid;

    // Phase A2: A_sm[grp] = lstm[b,t0+grp].w_l + w_t*(t0+grp) + bc
    // 64 groups of 8 threads; each thread 8 float4 (32 floats).
    {
        int grp = tid >> 3, l8 = tid & 7;
        const float4* row4 = (const float4*)(lstm + ((long)(b * T1 + t0 + grp)) * DLN);
        const float4* wl4  = (const float4*)w_char;
        float pv = 0.0f;
#pragma unroll
        for (int k = 0; k < 8; k++) {
            float4 rv = row4[l8 + 8 * k], wv = wl4[l8 + 8 * k];
            pv += rv.x * wv.x + rv.y * wv.y + rv.z * wv.z + rv.w * wv.w;
        }
#pragma unroll
        for (int off = 4; off; off >>= 1)
            pv += __shfl_xor_sync(0xffffffffu, pv, off);
        if (l8 == 0)
            A_sm[grp] = pv + w_char[DLN + CTXD] * (float)(t0 + grp) + b_char[0];
    }
    __syncthreads();

    // Phase B1: char_weights = A + g[s]  (64 t x 128 s, 16 uniform iters)
    {
        float* cwb = out_cw + ((long)(b * T1 + t0)) * T2;
#pragma unroll
        for (int it = 0; it < 16; it++) {
            int idx = tid + it * 512;
            int tl = idx >> 7, s = idx & (T2 - 1);
            cwb[tl * T2 + s] = A_sm[tl] + garr[s];
        }
    }

    // Phase B2: slab fill — slope/base for (126 s x 64 o) into smem.
    {
        int ocol = tid & 63;                      // constant across iters (512%64==0)
        float b2 = g_bias2[ocol];
        const float* Qb = g_Q00 + b * T2 * EE;
        const float* Qmb = g_Qm + b * T2 * EE;
        const float* Q1b = g_Q11 + b * T2 * EE;
        for (int idx = tid; idx < NS * EE; idx += 512) {
            int s = idx >> 6;
            float q0 = Qb [idx];                          // (s)   * EE + o
            float qm = Qmb[idx + EE];                     // (s+1) * EE + o
            float q1 = Q1b[idx + 2 * EE];                 // (s+2) * EE + o
            float slope = (q0 + qm) + q1;
            float base  = fmaf(garr[s], q0,
                          fmaf(garr[s + 1], qm,
                          fmaf(garr[s + 2], q1, b2)));
            sb_sm[idx] = make_float2(slope, base);
        }
    }
    __syncthreads();

    // Phase C: out[t,o] = max_s fma(A_t, slope[s,o], base[s,o]); 8 t per thread.
    {
        int tg = tid >> 6, o = tid & 63;
        float A0 = A_sm[tg + 0],  A1 = A_sm[tg + 8],  A2 = A_sm[tg + 16], A3 = A_sm[tg + 24];
        float A4 = A_sm[tg + 32], A5 = A_sm[tg + 40], A6 = A_sm[tg + 48], A7 = A_sm[tg + 56];
        float m0 = -INFINITY, m1 = -INFINITY, m2 = -INFINITY, m3 = -INFINITY;
        float m4 = -INFINITY, m5 = -INFINITY, m6 = -INFINITY, m7 = -INFINITY;
        const float2* sb = sb_sm + o;
#pragma unroll 2
        for (int s = 0; s < NS; s++) {
            float2 v = sb[s * EE];
            m0 = fmaxf(m0, fmaf(A0, v.x, v.y));
            m1 = fmaxf(m1, fmaf(A1, v.x, v.y));
            m2 = fmaxf(m2, fmaf(A2, v.x, v.y));
            m3 = fmaxf(m3, fmaf(A3, v.x, v.y));
            m4 = fmaxf(m4, fmaf(A4, v.x, v.y));
            m5 = fmaxf(m5, fmaf(A5, v.x, v.y));
            m6 = fmaxf(m6, fmaf(A6, v.x, v.y));
            m7 = fmaxf(m7, fmaf(A7, v.x, v.y));
        }
        long ob = (long)(b * T1 + t0) * EE + o;
        out_final[ob + (tg + 0)  * EE] = m0;
        out_final[ob + (tg + 8)  * EE] = m1;
        out_final[ob + (tg + 16) * EE] = m2;
        out_final[ob + (tg + 24) * EE] = m3;
        out_final[ob + (tg + 32) * EE] = m4;
        out_final[ob + (tg + 40) * EE] = m5;
        out_final[ob + (tg + 48) * EE] = m6;
        out_final[ob + (tg + 56) * EE] = m7;
    }
}

// ---------------------------------------------------------------------------
extern "C" void kernel_launch(void* const* d_in, const int* in_sizes, int n_in,
                              void* d_out, int out_size) {
    const float* lstm     = (const float*)d_in[0];
    const int*   char_seq = (const int*)  d_in[1];
    const float* emb      = (const float*)d_in[2];
    const float* Kf       = (const float*)d_in[3];
    const float* Rf       = (const float*)d_in[4];
    const float* bf       = (const float*)d_in[5];
    const float* Kb       = (const float*)d_in[6];
    const float* Rb       = (const float*)d_in[7];
    const float* bb       = (const float*)d_in[8];
    const float* w_char   = (const float*)d_in[9];
    const float* b_char   = (const float*)d_in[10];
    const float* conv1_w  = (const float*)d_in[11];
    const float* conv1_b  = (const float*)d_in[12];
    const float* conv2_w  = (const float*)d_in[13];
    const float* conv2_b  = (const float*)d_in[14];

    float* out_final = (float*)d_out;                 // (8,512,64)
    float* out_cw    = out_final + NB * T1 * EE;      // (8,512,128,1)

    (void)cudaFuncSetAttribute(k_gru, cudaFuncAttributeMaxDynamicSharedMemorySize,
                               T2 * G3 * (int)sizeof(float));
    (void)cudaFuncSetAttribute(k_main, cudaFuncAttributeMaxDynamicSharedMemorySize,
                               NS * EE * (int)sizeof(float2));

    k_tab<<<dim3(VOC, 2), G3>>>(emb, Kf, bf, Kb, bb);
    k_gru<<<dim3(NB, 2), 384, T2 * G3 * sizeof(float)>>>(char_seq, Rf, bf, Rb, bb);
    k_pq<<<NB * T2, CTXD>>>(conv1_w, conv2_w, conv1_b, conv2_b, w_char);
    k_main<<<dim3(NB, 8), 512, NS * EE * sizeof(float2)>>>(lstm, w_char, b_char,
                                                           out_final, out_cw);
}

// round 10
// speedup vs baseline: 1.1840x; 1.0706x over previous
#include <cuda_runtime.h>
#include <math.h>

// Problem constants
#define NB   8
#define T1   512
#define T2   128
#define EE   64      // E
#define G3   192     // 3*E
#define DLN  256
#define CTXD 128     // 2*E
#define VOC  129     // LA+1
#define NS   126     // T2-2 valid conv output positions
#define SLAB 128     // padded slab rows (power of 2)

// Scratch (device globals)
__device__ float g_tab[2 * VOC * G3];        // per-dir input-gate table
__device__ float g_ctx[NB * T2 * CTXD];      // [b][s][fwd|bwd]
__device__ float g_Q00[NB * T2 * EE];
__device__ float g_Qm [NB * T2 * EE];
__device__ float g_Q11[NB * T2 * EE];
__device__ float g_cs[NB * T2];              // ctx . w_c
__device__ float g_bias2[EE];

__device__ __forceinline__ float fsigmoid(float v) {
    return __fdividef(1.0f, 1.0f + __expf(-v));
}
__device__ __forceinline__ float ftanh(float v) {
    return fmaf(2.0f, __fdividef(1.0f, 1.0f + __expf(-2.0f * v)), -1.0f);
}

// ---------------------------------------------------------------------------
// Kernel T: input-gate table  tab[dir][c][u] = emb[c]@K_dir + b0[u]
// grid (129,2), block 192
// ---------------------------------------------------------------------------
__global__ void k_tab(const float* __restrict__ emb_table,
                      const float* __restrict__ Kf, const float* __restrict__ bf,
                      const float* __restrict__ Kb, const float* __restrict__ bb) {
    int c = blockIdx.x, dir = blockIdx.y;
    int u = threadIdx.x;
    __shared__ float e_sm[EE];
    if (u < EE) e_sm[u] = emb_table[c * EE + u];
    __syncthreads();
    const float* K = dir ? Kb : Kf;
    float a0 = (dir ? bb : bf)[u], a1 = 0.f, a2 = 0.f, a3 = 0.f;
    const float4* e4 = (const float4*)e_sm;
#pragma unroll
    for (int k = 0; k < 16; k++) {
        float4 hv = e4[k];
        int e = 4 * k;
        a0 = fmaf(hv.x, K[(e + 0) * G3 + u], a0);
        a1 = fmaf(hv.y, K[(e + 1) * G3 + u], a1);
        a2 = fmaf(hv.z, K[(e + 2) * G3 + u], a2);
        a3 = fmaf(hv.w, K[(e + 3) * G3 + u], a3);
    }
    g_tab[(dir * VOC + c) * G3 + u] = (a0 + a1) + (a2 + a3);
}

// ---------------------------------------------------------------------------
// Kernel G: GRU. grid (8,2), block 384 (= 192 cols x 2 e-halves).
// All x pre-staged in smem; 2 barriers/step; 4-acc matvec + 1 shfl.
// ---------------------------------------------------------------------------
__global__ void __launch_bounds__(384) k_gru(const int* __restrict__ char_seq,
                      const float* __restrict__ Rf, const float* __restrict__ bf,
                      const float* __restrict__ Rb, const float* __restrict__ bb) {
    extern __shared__ float x_sm[];              // [128][192]
    __shared__ float h_sm[EE];
    __shared__ float z_sm[EE];
    __shared__ float r_sm[EE];
    __shared__ int   s_char[T2];
    int b = blockIdx.x, dir = blockIdx.y;
    int tid = threadIdx.x;
    int col = tid >> 1, half = tid & 1;
    int gate = col >> 6, i = col & 63;

    const float* R    = dir ? Rb : Rf;
    const float* bias = dir ? bb : bf;
    float Rc[32];
#pragma unroll
    for (int e = 0; e < 32; e++) Rc[e] = R[(half * 32 + e) * G3 + col];
    float bcol = (half == 0) ? bias[G3 + col] : 0.0f;

    if (tid < T2) s_char[tid] = char_seq[b * T2 + tid];
    if (tid < EE) h_sm[tid] = 0.0f;
    __syncthreads();

    const float* tab = g_tab + dir * VOC * G3;
    for (int idx = tid; idx < T2 * G3; idx += 384) {
        int row = idx / G3, cc = idx - row * G3;
        x_sm[idx] = tab[s_char[row] * G3 + cc];
    }
    __syncthreads();

    float h = 0.0f, y = 0.0f;
    for (int t = 0; t < T2; t++) {
        int tt = dir ? (T2 - 1 - t) : t;
        float x = x_sm[tt * G3 + col];
        const float4* h4 = (const float4*)h_sm + half * 8;
        float a0 = bcol, a1 = 0.f, a2 = 0.f, a3 = 0.f;
#pragma unroll
        for (int k = 0; k < 8; k++) {
            float4 hv = h4[k];
            a0 = fmaf(hv.x, Rc[4 * k + 0], a0);
            a1 = fmaf(hv.y, Rc[4 * k + 1], a1);
            a2 = fmaf(hv.z, Rc[4 * k + 2], a2);
            a3 = fmaf(hv.w, Rc[4 * k + 3], a3);
        }
        float sum = (a0 + a1) + (a2 + a3);
        sum += __shfl_xor_sync(0xffffffffu, sum, 1);    // full rg(col)
        if (half == 0) {
            if (gate == 0)      z_sm[i] = fsigmoid(x + sum);
            else if (gate == 1) r_sm[i] = fsigmoid(x + sum);
        }
        __syncthreads();
        if (half == 0 && gate == 2) {
            float hh = ftanh(fmaf(r_sm[i], sum, x));
            float z  = z_sm[i];
            float hn = fmaf(z, h - hh, hh);              // z*h + (1-z)*hh
            if (s_char[tt] != 0) { h = hn; y = hn; }
            h_sm[i] = h;
            g_ctx[(b * T2 + tt) * CTXD + dir * EE + i] = y;
        }
        __syncthreads();
    }
}

// ---------------------------------------------------------------------------
// Kernel PQ: per (b,s): cs = ctx.w_c ; P0/P1 = ctx@W1 ; Q00/Qm/Q11 = P@W2
// grid 1024, block 128. 8-accumulator chains throughout.
// ---------------------------------------------------------------------------
__global__ void k_pq(const float* __restrict__ conv1_w,
                     const float* __restrict__ conv2_w,
                     const float* __restrict__ conv1_b,
                     const float* __restrict__ conv2_b,
                     const float* __restrict__ w_char) {
    int bs = blockIdx.x;
    int tid = threadIdx.x;
    __shared__ float c_sm[CTXD];
    __shared__ float wsum[4];
    __shared__ float p_sm[2][EE];
    __shared__ float q01_sm[EE];

    float cv = g_ctx[bs * CTXD + tid];
    c_sm[tid] = cv;
    float pv = cv * w_char[DLN + tid];
#pragma unroll
    for (int off = 16; off; off >>= 1) pv += __shfl_xor_sync(0xffffffffu, pv, off);
    if ((tid & 31) == 0) wsum[tid >> 5] = pv;
    __syncthreads();
    if (tid == 0) g_cs[bs] = (wsum[0] + wsum[1]) + (wsum[2] + wsum[3]);

    int half = tid >> 6, o = tid & 63;
    const float* W = conv1_w + half * CTXD * EE;
    float s0 = 0.f, s1 = 0.f, s2 = 0.f, s3 = 0.f;
    float s4 = 0.f, s5 = 0.f, s6 = 0.f, s7 = 0.f;
    const float4* c4 = (const float4*)c_sm;
#pragma unroll
    for (int k = 0; k < CTXD / 4; k += 2) {
        float4 h0 = c4[k], h1 = c4[k + 1];
        int c = 4 * k;
        s0 = fmaf(h0.x, W[(c + 0) * EE + o], s0);
        s1 = fmaf(h0.y, W[(c + 1) * EE + o], s1);
        s2 = fmaf(h0.z, W[(c + 2) * EE + o], s2);
        s3 = fmaf(h0.w, W[(c + 3) * EE + o], s3);
        s4 = fmaf(h1.x, W[(c + 4) * EE + o], s4);
        s5 = fmaf(h1.y, W[(c + 5) * EE + o], s5);
        s6 = fmaf(h1.z, W[(c + 6) * EE + o], s6);
        s7 = fmaf(h1.w, W[(c + 7) * EE + o], s7);
    }
    p_sm[half][o] = ((s0 + s1) + (s2 + s3)) + ((s4 + s5) + (s6 + s7));
    __syncthreads();

    const float* W20 = conv2_w;
    const float* W21 = conv2_w + EE * EE;
    const float* P = p_sm[half];
    float qa0 = 0.f, qa1 = 0.f, qa2 = 0.f, qa3 = 0.f;
    float qb0 = 0.f, qb1 = 0.f, qb2 = 0.f, qb3 = 0.f;
#pragma unroll
    for (int k = 0; k < EE; k += 4) {
        float p0 = P[k], p1 = P[k + 1], p2 = P[k + 2], p3 = P[k + 3];
        qa0 = fmaf(p0, W20[(k + 0) * EE + o], qa0);
        qb0 = fmaf(p0, W21[(k + 0) * EE + o], qb0);
        qa1 = fmaf(p1, W20[(k + 1) * EE + o], qa1);
        qb1 = fmaf(p1, W21[(k + 1) * EE + o], qb1);
        qa2 = fmaf(p2, W20[(k + 2) * EE + o], qa2);
        qb2 = fmaf(p2, W21[(k + 2) * EE + o], qb2);
        qa3 = fmaf(p3, W20[(k + 3) * EE + o], qa3);
        qb3 = fmaf(p3, W21[(k + 3) * EE + o], qb3);
    }
    float qW20 = (qa0 + qa1) + (qa2 + qa3);   // P@W20
    float qW21 = (qb0 + qb1) + (qb2 + qb3);   // P@W21
    if (half == 0) {
        g_Q00[bs * EE + o] = qW20;
        q01_sm[o] = qW21;
    }
    __syncthreads();
    if (half == 1) {
        g_Qm [bs * EE + o] = qW20 + q01_sm[o];   // P1@W20 + P0@W21
        g_Q11[bs * EE + o] = qW21;
    }
    if (bs == 0 && half == 0) {
        float bb2 = conv2_b[o];
#pragma unroll
        for (int k = 0; k < EE; k++)
            bb2 = fmaf(conv1_b[k], W20[k * EE + o] + W21[k * EE + o], bb2);
        g_bias2[o] = bb2;
    }
}

// ---------------------------------------------------------------------------
// Kernel D: smem slope/base slab + 4-way t-register-blocked max-plus.
// grid (8 b, 16 tb), block 512 (8 t-groups x 64 o). 32 t per block.
// Dynamic smem: float2 sb[128*64] = 64 KB (padded: s>=126 -> {0,-INF}).
// ---------------------------------------------------------------------------
__global__ void __launch_bounds__(512) k_main(const float* __restrict__ lstm,
                                              const float* __restrict__ w_char,
                                              const float* __restrict__ b_char,
                                              float* __restrict__ out_final,
                                              float* __restrict__ out_cw) {
    extern __shared__ float2 sb_sm[];            // [128*64] {slope, base}
    __shared__ float A_sm[32];
    __shared__ float garr[T2];
    int b = blockIdx.x, t0 = blockIdx.y * 32;
    int tid = threadIdx.x;

    // Phase A: garr[s] = cs + w_i*s
    float wi = w_char[DLN + CTXD + 1];
    if (tid < T2) garr[tid] = g_cs[b * T2 + tid] + wi * (float)tid;

    // Phase A2: A_sm[grp] = lstm[b,t0+grp].w_l + w_t*(t0+grp) + bc
    // 32 groups of 16 threads; each thread 4 float4 (16 floats).
    {
        int grp = tid >> 4, l16 = tid & 15;
        const float4* row4 = (const float4*)(lstm + ((long)(b * T1 + t0 + grp)) * DLN);
        const float4* wl4  = (const float4*)w_char;
        float pv = 0.0f;
#pragma unroll
        for (int k = 0; k < 4; k++) {
            float4 rv = row4[l16 + 16 * k], wv = wl4[l16 + 16 * k];
            pv += rv.x * wv.x + rv.y * wv.y + rv.z * wv.z + rv.w * wv.w;
        }
#pragma unroll
        for (int off = 8; off; off >>= 1)
            pv += __shfl_xor_sync(0xffffffffu, pv, off);
        if (l16 == 0)
            A_sm[grp] = pv + w_char[DLN + CTXD] * (float)(t0 + grp) + b_char[0];
    }
    __syncthreads();

    // Phase B1: char_weights = A + g[s]  (32 t x 128 s, 8 uniform iters)
    {
        float* cwb = out_cw + ((long)(b * T1 + t0)) * T2;
#pragma unroll
        for (int it = 0; it < 8; it++) {
            int idx = tid + it * 512;
            int tl = idx >> 7, s = idx & (T2 - 1);
            cwb[tl * T2 + s] = A_sm[tl] + garr[s];
        }
    }

    // Phase B2: slab fill — slope/base for (128 s x 64 o); s>=126 padded.
    {
        int ocol = tid & 63;                      // constant across iters (512%64==0)
        float b2 = g_bias2[ocol];
        const float* Qb  = g_Q00 + b * T2 * EE;
        const float* Qmb = g_Qm  + b * T2 * EE;
        const float* Q1b = g_Q11 + b * T2 * EE;
#pragma unroll
        for (int it = 0; it < 16; it++) {
            int idx = tid + it * 512;
            int s = idx >> 6;
            float slope = 0.0f, base = -INFINITY;
            if (s < NS) {
                float q0 = Qb [idx];                      // (s)   * EE + o
                float qm = Qmb[idx + EE];                 // (s+1) * EE + o
                float q1 = Q1b[idx + 2 * EE];             // (s+2) * EE + o
                slope = (q0 + qm) + q1;
                base  = fmaf(garr[s], q0,
                        fmaf(garr[s + 1], qm,
                        fmaf(garr[s + 2], q1, b2)));
            }
            sb_sm[idx] = make_float2(slope, base);
        }
    }
    __syncthreads();

    // Phase C: out[t,o] = max_s fma(A_t, slope[s,o], base[s,o]); 4 t per thread.
    {
        int tg = tid >> 6, o = tid & 63;
        float A0 = A_sm[tg + 0],  A1 = A_sm[tg + 8];
        float A2 = A_sm[tg + 16], A3 = A_sm[tg + 24];
        float m0 = -INFINITY, m1 = -INFINITY, m2 = -INFINITY, m3 = -INFINITY;
        const float2* sb = sb_sm + o;
#pragma unroll 8
        for (int s = 0; s < SLAB; s++) {
            float2 v = sb[s * EE];
            m0 = fmaxf(m0, fmaf(A0, v.x, v.y));
            m1 = fmaxf(m1, fmaf(A1, v.x, v.y));
            m2 = fmaxf(m2, fmaf(A2, v.x, v.y));
            m3 = fmaxf(m3, fmaf(A3, v.x, v.y));
        }
        long ob = (long)(b * T1 + t0) * EE + o;
        out_final[ob + (tg + 0)  * EE] = m0;
        out_final[ob + (tg + 8)  * EE] = m1;
        out_final[ob + (tg + 16) * EE] = m2;
        out_final[ob + (tg + 24) * EE] = m3;
    }
}

// ---------------------------------------------------------------------------
extern "C" void kernel_launch(void* const* d_in, const int* in_sizes, int n_in,
                              void* d_out, int out_size) {
    const float* lstm     = (const float*)d_in[0];
    const int*   char_seq = (const int*)  d_in[1];
    const float* emb      = (const float*)d_in[2];
    const float* Kf       = (const float*)d_in[3];
    const float* Rf       = (const float*)d_in[4];
    const float* bf       = (const float*)d_in[5];
    const float* Kb       = (const float*)d_in[6];
    const float* Rb       = (const float*)d_in[7];
    const float* bb       = (const float*)d_in[8];
    const float* w_char   = (const float*)d_in[9];
    const float* b_char   = (const float*)d_in[10];
    const float* conv1_w  = (const float*)d_in[11];
    const float* conv1_b  = (const float*)d_in[12];
    const float* conv2_w  = (const float*)d_in[13];
    const float* conv2_b  = (const float*)d_in[14];

    float* out_final = (float*)d_out;                 // (8,512,64)
    float* out_cw    = out_final + NB * T1 * EE;      // (8,512,128,1)

    (void)cudaFuncSetAttribute(k_gru, cudaFuncAttributeMaxDynamicSharedMemorySize,
                               T2 * G3 * (int)sizeof(float));
    (void)cudaFuncSetAttribute(k_main, cudaFuncAttributeMaxDynamicSharedMemorySize,
                               SLAB * EE * (int)sizeof(float2));

    k_tab<<<dim3(VOC, 2), G3>>>(emb, Kf, bf, Kb, bb);
    k_gru<<<dim3(NB, 2), 384, T2 * G3 * sizeof(float)>>>(char_seq, Rf, bf, Rb, bb);
    k_pq<<<NB * T2, CTXD>>>(conv1_w, conv2_w, conv1_b, conv2_b, w_char);
    k_main<<<dim3(NB, 16), 512, SLAB * EE * sizeof(float2)>>>(lstm, w_char, b_char,
                                                              out_final, out_cw);
}

// round 11
// speedup vs baseline: 1.4006x; 1.1830x over previous
#include <cuda_runtime.h>
#include <math.h>

// Problem constants
#define NB   8
#define T1   512
#define T2   128
#define EE   64      // E
#define G3   192     // 3*E
#define DLN  256
#define CTXD 128     // 2*E
#define VOC  129     // LA+1
#define NS   126     // T2-2 valid conv output positions
#define SLAB 128     // padded slab rows (power of 2)

// Scratch (device globals)
__device__ float g_tab[2 * VOC * G3];        // per-dir input-gate table
__device__ float g_ctx[NB * T2 * CTXD];      // [b][s][fwd|bwd]
__device__ float g_Q00[NB * T2 * EE];
__device__ float g_Qm [NB * T2 * EE];
__device__ float g_Q11[NB * T2 * EE];
__device__ float g_cs[NB * T2];              // ctx . w_c
__device__ float g_bias2[EE];

__device__ __forceinline__ float tanhapx(float v) {
    float r;
    asm("tanh.approx.f32 %0, %1;" : "=f"(r) : "f"(v));
    return r;
}
__device__ __forceinline__ float sigapx(float v) {
    return fmaf(0.5f, tanhapx(0.5f * v), 0.5f);
}
__device__ __forceinline__ unsigned long long packf2(float lo, float hi) {
    unsigned long long r;
    asm("mov.b64 %0, {%1, %2};" : "=l"(r) : "f"(lo), "f"(hi));
    return r;
}
__device__ __forceinline__ void fma2(unsigned long long& acc,
                                     unsigned long long a, unsigned long long b) {
    asm("fma.rn.f32x2 %0, %1, %2, %0;" : "+l"(acc) : "l"(a), "l"(b));
}
__device__ __forceinline__ float unpack_sum(unsigned long long v) {
    float lo, hi;
    asm("mov.b64 {%0, %1}, %2;" : "=f"(lo), "=f"(hi) : "l"(v));
    return lo + hi;
}

// ---------------------------------------------------------------------------
// Kernel T: input-gate table  tab[dir][c][u] = emb[c]@K_dir + b0[u]
// grid (129,2), block 192
// ---------------------------------------------------------------------------
__global__ void k_tab(const float* __restrict__ emb_table,
                      const float* __restrict__ Kf, const float* __restrict__ bf,
                      const float* __restrict__ Kb, const float* __restrict__ bb) {
    int c = blockIdx.x, dir = blockIdx.y;
    int u = threadIdx.x;
    __shared__ float e_sm[EE];
    if (u < EE) e_sm[u] = emb_table[c * EE + u];
    __syncthreads();
    const float* K = dir ? Kb : Kf;
    float a0 = (dir ? bb : bf)[u], a1 = 0.f, a2 = 0.f, a3 = 0.f;
    const float4* e4 = (const float4*)e_sm;
#pragma unroll
    for (int k = 0; k < 16; k++) {
        float4 hv = e4[k];
        int e = 4 * k;
        a0 = fmaf(hv.x, K[(e + 0) * G3 + u], a0);
        a1 = fmaf(hv.y, K[(e + 1) * G3 + u], a1);
        a2 = fmaf(hv.z, K[(e + 2) * G3 + u], a2);
        a3 = fmaf(hv.w, K[(e + 3) * G3 + u], a3);
    }
    g_tab[(dir * VOC + c) * G3 + u] = (a0 + a1) + (a2 + a3);
}

// ---------------------------------------------------------------------------
// Kernel G: GRU. grid (8,2), block 256 (64 units x 4 e-quarters).
// One barrier/step (ping-pong h). f32x2 packed FMA. tanh.approx activations.
// Intra-quad shfl for gate sums -> no z/r smem exchange.
// ---------------------------------------------------------------------------
__global__ void __launch_bounds__(256) k_gru(const int* __restrict__ char_seq,
                      const float* __restrict__ Rf, const float* __restrict__ bf,
                      const float* __restrict__ Rb, const float* __restrict__ bb) {
    extern __shared__ float x_sm[];              // [128][192]
    __shared__ float hbuf[2][EE];
    __shared__ int   s_char[T2];
    int b = blockIdx.x, dir = blockIdx.y;
    int tid = threadIdx.x;
    int i = tid >> 2, q = tid & 3;               // unit, e-quarter

    const float* R    = dir ? Rb : Rf;
    const float* bias = dir ? bb : bf;

    // Pack R column slices: gate g, e in [16q, 16q+16) as 8 f32x2 pairs each.
    unsigned long long Rz2[8], Rr2[8], Rh2[8];
#pragma unroll
    for (int k = 0; k < 8; k++) {
        int e = 16 * q + 2 * k;
        Rz2[k] = packf2(R[e * G3 + i],        R[(e + 1) * G3 + i]);
        Rr2[k] = packf2(R[e * G3 + 64 + i],   R[(e + 1) * G3 + 64 + i]);
        Rh2[k] = packf2(R[e * G3 + 128 + i],  R[(e + 1) * G3 + 128 + i]);
    }
    // Recurrent bias b1 folded into q==0 accumulator seed.
    float bz = (q == 0) ? bias[G3 + i]        : 0.0f;
    float br = (q == 0) ? bias[G3 + 64 + i]   : 0.0f;
    float bh = (q == 0) ? bias[G3 + 128 + i]  : 0.0f;

    if (tid < T2) s_char[tid] = char_seq[b * T2 + tid];
    if (tid < EE) hbuf[0][tid] = 0.0f;
    __syncthreads();

    const float* tab = g_tab + dir * VOC * G3;
    for (int idx = tid; idx < T2 * G3; idx += 256) {
        int row = idx / G3, cc = idx - row * G3;
        x_sm[idx] = tab[s_char[row] * G3 + cc];
    }
    __syncthreads();

    float h = 0.0f, y = 0.0f;
    int p = 0;
    for (int t = 0; t < T2; t++) {
        int tt = dir ? (T2 - 1 - t) : t;
        float xz = x_sm[tt * G3 + i];
        float xr = x_sm[tt * G3 + 64 + i];
        float xh = x_sm[tt * G3 + 128 + i];

        const unsigned long long* h2 =
            (const unsigned long long*)(hbuf[p] + 16 * q);
        unsigned long long az2 = packf2(bz, 0.0f);
        unsigned long long ar2 = packf2(br, 0.0f);
        unsigned long long ah2 = packf2(bh, 0.0f);
#pragma unroll
        for (int k = 0; k < 8; k++) {
            unsigned long long hv = h2[k];
            fma2(az2, hv, Rz2[k]);
            fma2(ar2, hv, Rr2[k]);
            fma2(ah2, hv, Rh2[k]);
        }
        float az = unpack_sum(az2);
        float ar = unpack_sum(ar2);
        float ah = unpack_sum(ah2);
        // reduce over the 4 quarter-lanes (lane bits 0-1)
        az += __shfl_xor_sync(0xffffffffu, az, 1);
        ar += __shfl_xor_sync(0xffffffffu, ar, 1);
        ah += __shfl_xor_sync(0xffffffffu, ah, 1);
        az += __shfl_xor_sync(0xffffffffu, az, 2);
        ar += __shfl_xor_sync(0xffffffffu, ar, 2);
        ah += __shfl_xor_sync(0xffffffffu, ah, 2);

        float z  = sigapx(xz + az);
        float r  = sigapx(xr + ar);
        float hh = tanhapx(fmaf(r, ah, xh));
        float hn = fmaf(z, h - hh, hh);              // z*h + (1-z)*hh
        if (s_char[tt] != 0) { h = hn; y = hn; }
        if (q == 0) {
            hbuf[1 - p][i] = h;
            g_ctx[(b * T2 + tt) * CTXD + dir * EE + i] = y;
        }
        p ^= 1;
        __syncthreads();
    }
}

// ---------------------------------------------------------------------------
// Kernel PQ: per (b,s): cs = ctx.w_c ; P0/P1 = ctx@W1 ; Q00/Qm/Q11 = P@W2
// grid 1024, block 128. 8-accumulator chains throughout.
// ---------------------------------------------------------------------------
__global__ void k_pq(const float* __restrict__ conv1_w,
                     const float* __restrict__ conv2_w,
                     const float* __restrict__ conv1_b,
                     const float* __restrict__ conv2_b,
                     const float* __restrict__ w_char) {
    int bs = blockIdx.x;
    int tid = threadIdx.x;
    __shared__ float c_sm[CTXD];
    __shared__ float wsum[4];
    __shared__ float p_sm[2][EE];
    __shared__ float q01_sm[EE];

    float cv = g_ctx[bs * CTXD + tid];
    c_sm[tid] = cv;
    float pv = cv * w_char[DLN + tid];
#pragma unroll
    for (int off = 16; off; off >>= 1) pv += __shfl_xor_sync(0xffffffffu, pv, off);
    if ((tid & 31) == 0) wsum[tid >> 5] = pv;
    __syncthreads();
    if (tid == 0) g_cs[bs] = (wsum[0] + wsum[1]) + (wsum[2] + wsum[3]);

    int half = tid >> 6, o = tid & 63;
    const float* W = conv1_w + half * CTXD * EE;
    float s0 = 0.f, s1 = 0.f, s2 = 0.f, s3 = 0.f;
    float s4 = 0.f, s5 = 0.f, s6 = 0.f, s7 = 0.f;
    const float4* c4 = (const float4*)c_sm;
#pragma unroll
    for (int k = 0; k < CTXD / 4; k += 2) {
        float4 h0 = c4[k], h1 = c4[k + 1];
        int c = 4 * k;
        s0 = fmaf(h0.x, W[(c + 0) * EE + o], s0);
        s1 = fmaf(h0.y, W[(c + 1) * EE + o], s1);
        s2 = fmaf(h0.z, W[(c + 2) * EE + o], s2);
        s3 = fmaf(h0.w, W[(c + 3) * EE + o], s3);
        s4 = fmaf(h1.x, W[(c + 4) * EE + o], s4);
        s5 = fmaf(h1.y, W[(c + 5) * EE + o], s5);
        s6 = fmaf(h1.z, W[(c + 6) * EE + o], s6);
        s7 = fmaf(h1.w, W[(c + 7) * EE + o], s7);
    }
    p_sm[half][o] = ((s0 + s1) + (s2 + s3)) + ((s4 + s5) + (s6 + s7));
    __syncthreads();

    const float* W20 = conv2_w;
    const float* W21 = conv2_w + EE * EE;
    const float* P = p_sm[half];
    float qa0 = 0.f, qa1 = 0.f, qa2 = 0.f, qa3 = 0.f;
    float qb0 = 0.f, qb1 = 0.f, qb2 = 0.f, qb3 = 0.f;
#pragma unroll
    for (int k = 0; k < EE; k += 4) {
        float p0 = P[k], p1 = P[k + 1], p2 = P[k + 2], p3 = P[k + 3];
        qa0 = fmaf(p0, W20[(k + 0) * EE + o], qa0);
        qb0 = fmaf(p0, W21[(k + 0) * EE + o], qb0);
        qa1 = fmaf(p1, W20[(k + 1) * EE + o], qa1);
        qb1 = fmaf(p1, W21[(k + 1) * EE + o], qb1);
        qa2 = fmaf(p2, W20[(k + 2) * EE + o], qa2);
        qb2 = fmaf(p2, W21[(k + 2) * EE + o], qb2);
        qa3 = fmaf(p3, W20[(k + 3) * EE + o], qa3);
        qb3 = fmaf(p3, W21[(k + 3) * EE + o], qb3);
    }
    float qW20 = (qa0 + qa1) + (qa2 + qa3);   // P@W20
    float qW21 = (qb0 + qb1) + (qb2 + qb3);   // P@W21
    if (half == 0) {
        g_Q00[bs * EE + o] = qW20;
        q01_sm[o] = qW21;
    }
    __syncthreads();
    if (half == 1) {
        g_Qm [bs * EE + o] = qW20 + q01_sm[o];   // P1@W20 + P0@W21
        g_Q11[bs * EE + o] = qW21;
    }
    if (bs == 0 && half == 0) {
        float bb2 = conv2_b[o];
#pragma unroll
        for (int k = 0; k < EE; k++)
            bb2 = fmaf(conv1_b[k], W20[k * EE + o] + W21[k * EE + o], bb2);
        g_bias2[o] = bb2;
    }
}

// ---------------------------------------------------------------------------
// Kernel D: smem slope/base slab + 4-way t-register-blocked max-plus.
// grid (8 b, 16 tb), block 512 (8 t-groups x 64 o). 32 t per block.
// Dynamic smem: float2 sb[128*64] = 64 KB (padded: s>=126 -> {0,-INF}).
// ---------------------------------------------------------------------------
__global__ void __launch_bounds__(512) k_main(const float* __restrict__ lstm,
                                              const float* __restrict__ w_char,
                                              const float* __restrict__ b_char,
                                              float* __restrict__ out_final,
                                              float* __restrict__ out_cw) {
    extern __shared__ float2 sb_sm[];            // [128*64] {slope, base}
    __shared__ float A_sm[32];
    __shared__ float garr[T2];
    int b = blockIdx.x, t0 = blockIdx.y * 32;
    int tid = threadIdx.x;

    float wi = w_char[DLN + CTXD + 1];
    if (tid < T2) garr[tid] = g_cs[b * T2 + tid] + wi * (float)tid;

    {
        int grp = tid >> 4, l16 = tid & 15;
        const float4* row4 = (const float4*)(lstm + ((long)(b * T1 + t0 + grp)) * DLN);
        const float4* wl4  = (const float4*)w_char;
        float pv = 0.0f;
#pragma unroll
        for (int k = 0; k < 4; k++) {
            float4 rv = row4[l16 + 16 * k], wv = wl4[l16 + 16 * k];
            pv += rv.x * wv.x + rv.y * wv.y + rv.z * wv.z + rv.w * wv.w;
        }
#pragma unroll
        for (int off = 8; off; off >>= 1)
            pv += __shfl_xor_sync(0xffffffffu, pv, off);
        if (l16 == 0)
            A_sm[grp] = pv + w_char[DLN + CTXD] * (float)(t0 + grp) + b_char[0];
    }
    __syncthreads();

    {
        float* cwb = out_cw + ((long)(b * T1 + t0)) * T2;
#pragma unroll
        for (int it = 0; it < 8; it++) {
            int idx = tid + it * 512;
            int tl = idx >> 7, s = idx & (T2 - 1);
            cwb[tl * T2 + s] = A_sm[tl] + garr[s];
        }
    }

    {
        int ocol = tid & 63;
        float b2 = g_bias2[ocol];
        const float* Qb  = g_Q00 + b * T2 * EE;
        const float* Qmb = g_Qm  + b * T2 * EE;
        const float* Q1b = g_Q11 + b * T2 * EE;
#pragma unroll
        for (int it = 0; it < 16; it++) {
            int idx = tid + it * 512;
            int s = idx >> 6;
            float slope = 0.0f, base = -INFINITY;
            if (s < NS) {
                float q0 = Qb [idx];
                float qm = Qmb[idx + EE];
                float q1 = Q1b[idx + 2 * EE];
                slope = (q0 + qm) + q1;
                base  = fmaf(garr[s], q0,
                        fmaf(garr[s + 1], qm,
                        fmaf(garr[s + 2], q1, b2)));
            }
            sb_sm[idx] = make_float2(slope, base);
        }
    }
    __syncthreads();

    {
        int tg = tid >> 6, o = tid & 63;
        float A0 = A_sm[tg + 0],  A1 = A_sm[tg + 8];
        float A2 = A_sm[tg + 16], A3 = A_sm[tg + 24];
        float m0 = -INFINITY, m1 = -INFINITY, m2 = -INFINITY, m3 = -INFINITY;
        const float2* sb = sb_sm + o;
#pragma unroll 8
        for (int s = 0; s < SLAB; s++) {
            float2 v = sb[s * EE];
            m0 = fmaxf(m0, fmaf(A0, v.x, v.y));
            m1 = fmaxf(m1, fmaf(A1, v.x, v.y));
            m2 = fmaxf(m2, fmaf(A2, v.x, v.y));
            m3 = fmaxf(m3, fmaf(A3, v.x, v.y));
        }
        long ob = (long)(b * T1 + t0) * EE + o;
        out_final[ob + (tg + 0)  * EE] = m0;
        out_final[ob + (tg + 8)  * EE] = m1;
        out_final[ob + (tg + 16) * EE] = m2;
        out_final[ob + (tg + 24) * EE] = m3;
    }
}

// ---------------------------------------------------------------------------
extern "C" void kernel_launch(void* const* d_in, const int* in_sizes, int n_in,
                              void* d_out, int out_size) {
    const float* lstm     = (const float*)d_in[0];
    const int*   char_seq = (const int*)  d_in[1];
    const float* emb      = (const float*)d_in[2];
    const float* Kf       = (const float*)d_in[3];
    const float* Rf       = (const float*)d_in[4];
    const float* bf       = (const float*)d_in[5];
    const float* Kb       = (const float*)d_in[6];
    const float* Rb       = (const float*)d_in[7];
    const float* bb       = (const float*)d_in[8];
    const float* w_char   = (const float*)d_in[9];
    const float* b_char   = (const float*)d_in[10];
    const float* conv1_w  = (const float*)d_in[11];
    const float* conv1_b  = (const float*)d_in[12];
    const float* conv2_w  = (const float*)d_in[13];
    const float* conv2_b  = (const float*)d_in[14];

    float* out_final = (float*)d_out;                 // (8,512,64)
    float* out_cw    = out_final + NB * T1 * EE;      // (8,512,128,1)

    (void)cudaFuncSetAttribute(k_gru, cudaFuncAttributeMaxDynamicSharedMemorySize,
                               T2 * G3 * (int)sizeof(float));
    (void)cudaFuncSetAttribute(k_main, cudaFuncAttributeMaxDynamicSharedMemorySize,
                               SLAB * EE * (int)sizeof(float2));

    k_tab<<<dim3(VOC, 2), G3>>>(emb, Kf, bf, Kb, bb);
    k_gru<<<dim3(NB, 2), 256, T2 * G3 * sizeof(float)>>>(char_seq, Rf, bf, Rb, bb);
    k_pq<<<NB * T2, CTXD>>>(conv1_w, conv2_w, conv1_b, conv2_b, w_char);
    k_main<<<dim3(NB, 16), 512, SLAB * EE * sizeof(float2)>>>(lstm, w_char, b_char,
                                                              out_final, out_cw);
}